// round 12
// baseline (speedup 1.0000x reference)
#include <cuda_runtime.h>
#include <cuda_bf16.h>
#include <cstdint>
#include <cstddef>

#define ED 1024
#define BD 2048
#define BA 128
#define NITER 500
#define LAMB_C 0.3f
#define H_C 0.005f
#define RMC 0.99f
#define LOWACT 0.001f
#define GRIDP 256

#define O_A     ((size_t)0)
#define O_BASIS ((size_t)(BD*BA))
#define O_HES   (O_BASIS + (size_t)ED*BD)
#define O_L1    (O_HES + BD)
#define O_SNR   (O_L1 + BD)

// mmant_k smem (256 thr, tile 32x64): 4-stage ring, 144B rows
#define GH_O 0
#define GL_O 4608
#define BH_O 9216
#define BL_O 18432
#define BUFS 28672
#define DYN  (4*BUFS)
// persist4_k smem (128 thr, tile 32x32): G rows 144B, a rows 80B
#define GH2 0
#define GL2 4608
#define AH2 9216
#define AL2 14336
#define BUFS2 19456
#define DYN2 (4*BUFS2)

typedef __nv_bfloat16 bf16;

__device__ float g_BT[(size_t)BD*ED];
__device__ float g_It[(size_t)ED*BA];
__device__ float g_a [(size_t)BD*BA];
__device__ float g_a2[(size_t)BD*BA];
__device__ float g_c [(size_t)BD*BA];
__device__ float g_r [(size_t)ED*BA];
__device__ float g_S [(size_t)ED*ED];
__device__ float g_T0[(size_t)ED*ED];
__device__ float g_T1[(size_t)ED*ED];
__device__ float g_NB[(size_t)ED*BD];
__device__ float g_aT[(size_t)BA*BD];
__device__ bf16 g_Gh[(size_t)BD*BD];
__device__ bf16 g_Gl[(size_t)BD*BD];
__device__ bf16 g_ah0[(size_t)BD*BA];
__device__ bf16 g_ah1[(size_t)BD*BA];
__device__ bf16 g_al0[(size_t)BD*BA];
__device__ bf16 g_al1[(size_t)BD*BA];
__device__ bf16 g_Th0[(size_t)ED*ED];
__device__ bf16 g_Tl0[(size_t)ED*ED];
__device__ bf16 g_Th1[(size_t)ED*ED];
__device__ bf16 g_Tl1[(size_t)ED*ED];
__device__ bf16 g_BTh[(size_t)BD*ED];
__device__ bf16 g_BTl[(size_t)BD*ED];
__device__ bf16 g_bsh[(size_t)ED*BD];
__device__ bf16 g_bsl[(size_t)ED*BD];
__device__ bf16 g_Ith[(size_t)ED*BA];
__device__ bf16 g_Itl[(size_t)ED*BA];
__device__ bf16 g_rh[(size_t)ED*BA];
__device__ bf16 g_rl[(size_t)ED*BA];
__device__ bf16 g_aTh[(size_t)BA*BD];
__device__ bf16 g_aTl[(size_t)BA*BD];
__device__ float g_hes[BD];
__device__ float g_nsq[BD];
__device__ float g_v[ED];
__device__ float g_w[ED];
__device__ float g_scal[8];
__device__ unsigned g_cnt;
__device__ volatile unsigned g_gen;

__device__ __forceinline__ float sshrinkf(float v, float thr) {
    float t = fabsf(v) - thr;
    return t > 0.0f ? copysignf(t, v) : 0.0f;
}
__device__ __forceinline__ uint32_t smem_u32(const void* p) {
    uint32_t a;
    asm("{ .reg .u64 t; cvta.to.shared.u64 t, %1; cvt.u32.u64 %0, t; }" : "=r"(a) : "l"(p));
    return a;
}
#define LDSM4(r, ad) asm volatile( \
    "ldmatrix.sync.aligned.m8n8.x4.shared.b16 {%0,%1,%2,%3},[%4];" \
    : "=r"((r)[0]),"=r"((r)[1]),"=r"((r)[2]),"=r"((r)[3]) : "r"(ad))
#define LDSM4T(r, ad) asm volatile( \
    "ldmatrix.sync.aligned.m8n8.x4.trans.shared.b16 {%0,%1,%2,%3},[%4];" \
    : "=r"((r)[0]),"=r"((r)[1]),"=r"((r)[2]),"=r"((r)[3]) : "r"(ad))
#define MMA16816(c, a, b0, b1) asm volatile( \
    "mma.sync.aligned.m16n8k16.row.col.f32.bf16.bf16.f32 " \
    "{%0,%1,%2,%3},{%4,%5,%6,%7},{%8,%9},{%0,%1,%2,%3};" \
    : "+f"((c)[0]),"+f"((c)[1]),"+f"((c)[2]),"+f"((c)[3]) \
    : "r"((a)[0]),"r"((a)[1]),"r"((a)[2]),"r"((a)[3]),"r"(b0),"r"(b1))
#define CPA16(dst, src) asm volatile("cp.async.cg.shared.global [%0],[%1],16;" :: "r"(dst), "l"(src))
#define CPCOMMIT() asm volatile("cp.async.commit_group;" ::: "memory")
#define CPWAIT(n)  asm volatile("cp.async.wait_group %0;" :: "n"(n) : "memory")

__device__ __forceinline__ void gsync(unsigned gen) {
    __syncthreads();
    if (threadIdx.x == 0) {
        __threadfence();
        unsigned t = atomicAdd(&g_cnt, 1u);
        if (t == GRIDP - 1) { g_cnt = 0; __threadfence(); g_gen = gen; }
        else { while (g_gen < gen) { } __threadfence(); }
    }
    __syncthreads();
}

// =================== generic split-bf16 NT GEMM on mma ===================
// C[M,N] = A(Ah+Al)[M,K] * B(Bh+Bl)^T where B is stored K-major [K][N].
// grid (N/64, M/32), 256 threads. EPI 0: Cf  1: Cf*s2 + split  2: NB-update  3: split only
template<int EPI>
__global__ void __launch_bounds__(256, 1) mmant_k(
    const bf16* __restrict__ Ah, const bf16* __restrict__ Al,
    const bf16* __restrict__ Bh, const bf16* __restrict__ Bl,
    float* __restrict__ Cf, const float* __restrict__ Aux,
    bf16* __restrict__ Ch, bf16* __restrict__ Cl, int N, int K)
{
    extern __shared__ char dsm[];
    const int tid = threadIdx.x, w = tid >> 5, l = tid & 31;
    const int nt = blockIdx.x, mt = blockIdx.y;
    const int wm = w >> 2, wn = w & 3;
    const uint32_t smu = smem_u32(dsm);
    const uint32_t adA = (uint32_t)(wm*16 + (l & 15))*144 + ((l >> 4)*16);
    const uint32_t adB = (uint32_t)((l & 7) + ((l >> 3) & 1)*8)*144 + (wn*32 + (l >> 4)*16);
    const int KT = K >> 6;
    float acc0[4] = {0,0,0,0}, acc1[4] = {0,0,0,0};

    auto ISS = [&](int t) {
        uint32_t sb = smu + (uint32_t)(t & 3)*BUFS;
        int kc = t*64;
        { int r_ = tid >> 3, q = tid & 7;
          CPA16(sb + GH_O + r_*144 + q*16, Ah + (size_t)(mt*32 + r_)*K + kc + q*8);
          CPA16(sb + GL_O + r_*144 + q*16, Al + (size_t)(mt*32 + r_)*K + kc + q*8); }
        #pragma unroll
        for (int i = 0; i < 2; i++) {
            int u = tid*2 + i, r_ = u >> 3, q = u & 7;
            CPA16(sb + BH_O + r_*144 + q*16, Bh + (size_t)(kc + r_)*N + nt*64 + q*8);
            CPA16(sb + BL_O + r_*144 + q*16, Bl + (size_t)(kc + r_)*N + nt*64 + q*8);
        }
        CPCOMMIT();
    };
    ISS(0);
    if (KT > 1) ISS(1);
    if (KT > 2) ISS(2);

    #pragma unroll 1
    for (int t = 0; t < KT; t++) {
        int rem = ((t + 3 < KT) ? 3 : (KT - t)) - 1;
        if (rem >= 2) CPWAIT(2); else if (rem == 1) CPWAIT(1); else CPWAIT(0);
        __syncthreads();
        if (t + 3 < KT) ISS(t + 3);
        const uint32_t base = smu + (uint32_t)(t & 3)*BUFS;
        #pragma unroll
        for (int kq = 0; kq < 4; kq++) {
            uint32_t fah[4], fal[4], fbh[4], fbl[4];
            LDSM4(fah, base + GH_O + kq*32 + adA);
            LDSM4(fal, base + GL_O + kq*32 + adA);
            LDSM4T(fbh, base + BH_O + kq*16*144 + adB);
            LDSM4T(fbl, base + BL_O + kq*16*144 + adB);
            MMA16816(acc0, fah, fbh[0], fbh[1]);
            MMA16816(acc1, fah, fbh[2], fbh[3]);
            MMA16816(acc0, fah, fbl[0], fbl[1]);
            MMA16816(acc1, fah, fbl[2], fbl[3]);
            MMA16816(acc0, fal, fbh[0], fbh[1]);
            MMA16816(acc1, fal, fbh[2], fbh[3]);
        }
    }
    const float s2 = (EPI == 1) ? g_scal[3]*g_scal[3] : 1.0f;
    #pragma unroll
    for (int ntl = 0; ntl < 2; ntl++) {
        const float* ap = ntl ? acc1 : acc0;
        int gc = nt*64 + wn*16 + ntl*8 + (l & 3)*2;
        #pragma unroll
        for (int rr = 0; rr < 2; rr++) {
            int gr = mt*32 + wm*16 + (l >> 2) + rr*8;
            size_t idx = (size_t)gr*N + gc;
            float vx = ap[rr*2+0], vy = ap[rr*2+1];
            if (EPI == 0) {
                *(float2*)&Cf[idx] = make_float2(vx, vy);
            } else if (EPI == 1) {
                vx *= s2; vy *= s2;
                *(float2*)&Cf[idx] = make_float2(vx, vy);
                __nv_bfloat162 hp, lp;
                hp.x = __float2bfloat16(vx); hp.y = __float2bfloat16(vy);
                lp.x = __float2bfloat16(vx - __bfloat162float(hp.x));
                lp.y = __float2bfloat16(vy - __bfloat162float(hp.y));
                *(__nv_bfloat162*)&Ch[idx] = hp;
                *(__nv_bfloat162*)&Cl[idx] = lp;
            } else if (EPI == 2) {
                float2 ax = *(const float2*)&Aux[idx];
                Cf[idx]   = ax.x + (H_C/(float)BA)*vx/(g_hes[gc]   + LOWACT);
                Cf[idx+1] = ax.y + (H_C/(float)BA)*vy/(g_hes[gc+1] + LOWACT);
            } else {
                __nv_bfloat162 hp, lp;
                hp.x = __float2bfloat16(vx); hp.y = __float2bfloat16(vy);
                lp.x = __float2bfloat16(vx - __bfloat162float(hp.x));
                lp.y = __float2bfloat16(vy - __bfloat162float(hp.y));
                *(__nv_bfloat162*)&Ch[idx] = hp;
                *(__nv_bfloat162*)&Cl[idx] = lp;
            }
        }
    }
}

// ========== persistent: power iter + 500 Gram-ISTA iters (2 CTA/SM) ==========
__global__ void __launch_bounds__(128, 2) persist4_k(const float* __restrict__ basis)
{
    extern __shared__ char dsm[];
    __shared__ float red1[4], red2[4];
    __shared__ float sh_b;
    const int cta = blockIdx.x, tid = threadIdx.x;
    const int w = tid >> 5, l = tid & 31;
    unsigned gen = 0;
    const uint32_t smu = smem_u32(dsm);

    // ---- power iteration: 8 matvecs on dir(S^64) (g_T0), then S + Rayleigh ----
    for (int pi = 0; pi < 9; pi++) {
        const float* M = (pi < 8) ? g_T0 : g_S;
        {
            int rw = cta*4 + w;
            const float* mr = M + (size_t)rw*ED;
            float s = 0.f;
            for (int j = l; j < ED; j += 32) s = fmaf(mr[j], g_v[j], s);
            #pragma unroll
            for (int o = 16; o; o >>= 1) s += __shfl_xor_sync(~0u, s, o);
            if (l == 0) g_w[rw] = s;
        }
        gen++; gsync(gen);
        if (cta == 0) {
            if (pi < 8) {
                float x[8], ss = 0.f;
                #pragma unroll
                for (int i = 0; i < 8; i++) { x[i] = g_w[tid*8+i]; ss = fmaf(x[i], x[i], ss); }
                #pragma unroll
                for (int o = 16; o; o >>= 1) ss += __shfl_xor_sync(~0u, ss, o);
                if (l == 0) red1[w] = ss;
                __syncthreads();
                if (tid == 0) sh_b = rsqrtf(red1[0]+red1[1]+red1[2]+red1[3]);
                __syncthreads();
                float rs = sh_b;
                #pragma unroll
                for (int i = 0; i < 8; i++) g_v[tid*8+i] = x[i]*rs;
            } else {
                float d1 = 0.f, d2 = 0.f;
                #pragma unroll
                for (int i = 0; i < 8; i++) {
                    float vv = g_v[tid*8+i], ww = g_w[tid*8+i];
                    d1 = fmaf(vv, ww, d1); d2 = fmaf(vv, vv, d2);
                }
                #pragma unroll
                for (int o = 16; o; o >>= 1) {
                    d1 += __shfl_xor_sync(~0u, d1, o);
                    d2 += __shfl_xor_sync(~0u, d2, o);
                }
                if (l == 0) { red1[w] = d1; red2[w] = d2; }
                __syncthreads();
                if (tid == 0) {
                    float lam = (red1[0]+red1[1]+red1[2]+red1[3]) /
                                (red2[0]+red2[1]+red2[2]+red2[3]);
                    g_scal[0] = lam; g_scal[1] = 1.0f/lam; g_scal[2] = LAMB_C/lam;
                }
                __syncthreads();
            }
        }
        gen++; gsync(gen);
    }

    const float eta = g_scal[1], thr = g_scal[2];
    const int mt = cta >> 2, nq = cta & 3;       // 64 M-tiles x 4 N-quarters
    const int wm = w >> 1, wn = w & 1;           // warp grid 2x2, tile 16x16
    const uint32_t adA = (uint32_t)(wm*16 + (l & 15))*144 + ((l >> 4)*16);
    const uint32_t adB = (uint32_t)((l & 7) + ((l >> 3) & 1)*8)*80 + (wn*32 + (l >> 4)*16);

    for (int it = 0; it < NITER; it++) {
        const int cur = it & 1;
        const float* acur = cur ? g_a2 : g_a;
        float*       anxt = cur ? g_a  : g_a2;
        const bf16* ahc = cur ? g_ah1 : g_ah0;
        const bf16* alc = cur ? g_al1 : g_al0;
        bf16* ahn = cur ? g_ah0 : g_ah1;
        bf16* aln = cur ? g_al0 : g_al1;

        float acc0[4] = {0,0,0,0}, acc1[4] = {0,0,0,0};
        auto ISS = [&](int t) {
            uint32_t sb = smu + (uint32_t)(t & 3)*BUFS2;
            int kc = t*64;
            #pragma unroll
            for (int i = 0; i < 2; i++) {
                int u = tid*2 + i;
                int gr_ = u >> 3, gq = u & 7;
                CPA16(sb + GH2 + gr_*144 + gq*16, g_Gh + (size_t)(mt*32+gr_)*BD + kc + gq*8);
                CPA16(sb + GL2 + gr_*144 + gq*16, g_Gl + (size_t)(mt*32+gr_)*BD + kc + gq*8);
                int ar_ = u >> 2, aq = u & 3;
                CPA16(sb + AH2 + ar_*80 + aq*16, ahc + (size_t)(kc+ar_)*BA + nq*32 + aq*8);
                CPA16(sb + AL2 + ar_*80 + aq*16, alc + (size_t)(kc+ar_)*BA + nq*32 + aq*8);
            }
            CPCOMMIT();
        };
        ISS(0); ISS(1); ISS(2);

        #pragma unroll 1
        for (int t = 0; t < 32; t++) {
            if (t < 30) CPWAIT(2); else if (t == 30) CPWAIT(1); else CPWAIT(0);
            __syncthreads();
            if (t + 3 < 32) ISS(t + 3);
            const uint32_t base = smu + (uint32_t)(t & 3)*BUFS2;
            #pragma unroll
            for (int kq = 0; kq < 4; kq++) {
                uint32_t fah[4], fal[4], fbh[4], fbl[4];
                LDSM4(fah, base + GH2 + kq*32 + adA);
                LDSM4(fal, base + GL2 + kq*32 + adA);
                LDSM4T(fbh, base + AH2 + kq*1280 + adB);
                LDSM4T(fbl, base + AL2 + kq*1280 + adB);
                MMA16816(acc0, fah, fbh[0], fbh[1]);
                MMA16816(acc1, fah, fbh[2], fbh[3]);
                MMA16816(acc0, fah, fbl[0], fbl[1]);
                MMA16816(acc1, fah, fbl[2], fbl[3]);
                MMA16816(acc0, fal, fbh[0], fbh[1]);
                MMA16816(acc1, fal, fbh[2], fbh[3]);
            }
        }

        #pragma unroll
        for (int nt = 0; nt < 2; nt++) {
            const float* ap = nt ? acc1 : acc0;
            int gc = nq*32 + wn*16 + nt*8 + (l & 3)*2;
            #pragma unroll
            for (int rr = 0; rr < 2; rr++) {
                int gr = mt*32 + wm*16 + (l >> 2) + rr*8;
                size_t idx = (size_t)gr*BA + gc;
                float2 ao = *(const float2*)&acur[idx];
                float2 cv = *(const float2*)&g_c[idx];
                float vx = sshrinkf(ao.x + eta*(cv.x - ap[rr*2+0]), thr);
                float vy = sshrinkf(ao.y + eta*(cv.y - ap[rr*2+1]), thr);
                *(float2*)&anxt[idx] = make_float2(vx, vy);
                __nv_bfloat162 hp, lp;
                hp.x = __float2bfloat16(vx); hp.y = __float2bfloat16(vy);
                lp.x = __float2bfloat16(vx - __bfloat162float(hp.x));
                lp.y = __float2bfloat16(vy - __bfloat162float(hp.y));
                *(__nv_bfloat162*)&ahn[idx] = hp;
                *(__nv_bfloat162*)&aln[idx] = lp;
            }
        }
        gen++; gsync(gen);
    }

    // ---- final residual: r = It - basis*a ; warp -> one row (256*4 = 1024) ----
    {
        const int rw = cta*4 + w;
        float4 racc = make_float4(0.f, 0.f, 0.f, 0.f);
        float* aS = (float*)dsm;                  // [32][132]
        float* bS = (float*)(dsm + 16896);        // [4][32]
        for (int t = 0; t < 64; t++) {
            int k0 = t*32;
            float4 rv[8];
            #pragma unroll
            for (int i = 0; i < 8; i++) {
                int u = tid*8 + i, rr = u >> 5, q = u & 31;
                rv[i] = *(const float4*)&g_a[(size_t)(k0 + rr)*BA + q*4];
            }
            float bb = basis[(size_t)rw*BD + k0 + l];
            __syncthreads();
            #pragma unroll
            for (int i = 0; i < 8; i++) {
                int u = tid*8 + i, rr = u >> 5, q = u & 31;
                *(float4*)&aS[rr*132 + q*4] = rv[i];
            }
            bS[w*32 + l] = bb;
            __syncthreads();
            #pragma unroll 8
            for (int kk = 0; kk < 32; kk++) {
                float b_ = bS[w*32 + kk];
                float4 av = *(const float4*)&aS[kk*132 + l*4];
                racc.x = fmaf(b_, av.x, racc.x);
                racc.y = fmaf(b_, av.y, racc.y);
                racc.z = fmaf(b_, av.z, racc.z);
                racc.w = fmaf(b_, av.w, racc.w);
            }
        }
        float4 iv = *(const float4*)&g_It[(size_t)rw*BA + l*4];
        *(float4*)&g_r[(size_t)rw*BA + l*4] =
            make_float4(iv.x-racc.x, iv.y-racc.y, iv.z-racc.z, iv.w-racc.w);
    }
}

// ---------------- helpers ----------------
__global__ void transpose_k(const float* __restrict__ in, float* __restrict__ out,
                            int rows, int cols)
{
    __shared__ float sm[32][33];
    int bx = blockIdx.x*32, by = blockIdx.y*32;
    int tx = threadIdx.x, ty = threadIdx.y;
    #pragma unroll
    for (int j = 0; j < 32; j += 8)
        sm[ty+j][tx] = in[(size_t)(by+ty+j)*cols + bx+tx];
    __syncthreads();
    #pragma unroll
    for (int j = 0; j < 32; j += 8)
        out[(size_t)(bx+ty+j)*rows + by+tx] = sm[tx][ty+j];
}

__global__ void init_k() {
    int idx = blockIdx.x*256 + threadIdx.x;
    if (idx < BD*BA) {
        g_a[idx] = 0.0f;
        g_ah0[idx] = __float2bfloat16(0.0f);
        g_al0[idx] = __float2bfloat16(0.0f);
    }
    if (idx < ED) g_v[idx] = 1.0f;
    if (idx == 0) { g_scal[4] = 0.0f; g_cnt = 0; g_gen = 0; }
}

__global__ void splitf_k(const float* __restrict__ in, bf16* __restrict__ h,
                         bf16* __restrict__ lo, int n)
{
    int i = blockIdx.x*256 + threadIdx.x;
    if (i < n) {
        float g = in[i];
        bf16 hh = __float2bfloat16(g);
        h[i] = hh;
        lo[i] = __float2bfloat16(g - __bfloat162float(hh));
    }
}

__global__ void copyN_k(const float* __restrict__ in, float* __restrict__ out, int n) {
    int i = blockIdx.x*256 + threadIdx.x;
    if (i < n) out[i] = in[i];
}

__global__ void diagmax_k(const float* __restrict__ T) {
    __shared__ float red[32];
    int tid = threadIdx.x;
    float m = fabsf(T[(size_t)tid*ED + tid]);
    #pragma unroll
    for (int o = 16; o; o >>= 1) m = fmaxf(m, __shfl_xor_sync(~0u, m, o));
    if ((tid&31)==0) red[tid>>5] = m;
    __syncthreads();
    if (tid < 32) {
        float mm = red[tid];
        #pragma unroll
        for (int o = 16; o; o >>= 1) mm = fmaxf(mm, __shfl_xor_sync(~0u, mm, o));
        if (tid == 0) g_scal[3] = 1.0f / mm;
    }
}

__global__ void rowstats_k(const float* __restrict__ a, const float* __restrict__ hd,
                           const float* __restrict__ l1h,
                           float* __restrict__ out_hes, float* __restrict__ out_l1)
{
    __shared__ float s1s[4], s2s[4];
    int m = blockIdx.x, tid = threadIdx.x;
    float av = a[(size_t)m*BA + tid];
    float s1 = fabsf(av), s2 = av*av;
    #pragma unroll
    for (int o = 16; o; o >>= 1) {
        s1 += __shfl_xor_sync(~0u, s1, o);
        s2 += __shfl_xor_sync(~0u, s2, o);
    }
    if ((tid&31)==0) { s1s[tid>>5]=s1; s2s[tid>>5]=s2; }
    __syncthreads();
    if (tid == 0) {
        float t1 = s1s[0]+s1s[1]+s1s[2]+s1s[3];
        float t2 = s2s[0]+s2s[1]+s2s[2]+s2s[3];
        float he = hd[m]*RMC + t2*(1.0f/(BA*100.0f));
        out_l1[m] = l1h[m]*RMC + t1*(1.0f/(BA*100.0f));
        out_hes[m] = he;
        g_hes[m] = he;
        g_nsq[m] = 0.0f;
    }
}

__global__ void colnorm1_k(const float* __restrict__ NB) {
    int col = blockIdx.x*256 + threadIdx.x;
    int r0 = blockIdx.y*128;
    float s = 0.0f;
    for (int r = r0; r < r0+128; r++) {
        float v = NB[(size_t)r*BD + col];
        s = fmaf(v, v, s);
    }
    atomicAdd(&g_nsq[col], s);
}

__global__ void colnorm2_k(const float* __restrict__ NB, float* __restrict__ out) {
    int i = blockIdx.x*blockDim.x + threadIdx.x;
    if (i < ED*BD) out[i] = NB[i] * rsqrtf(g_nsq[i & (BD-1)]);
}

__global__ void copy_a_k(const float* __restrict__ a, float* __restrict__ out) {
    int i = blockIdx.x*blockDim.x + threadIdx.x;
    if (i < BD*BA) out[i] = a[i];
}

__global__ void sumI2_k(const float* __restrict__ I) {
    __shared__ float red[8];
    int tid = threadIdx.x;
    float s = 0.0f;
    for (int i = blockIdx.x*blockDim.x + tid; i < ED*BA; i += gridDim.x*blockDim.x) {
        float v = I[i];
        s = fmaf(v, v, s);
    }
    #pragma unroll
    for (int o = 16; o; o >>= 1) s += __shfl_xor_sync(~0u, s, o);
    if ((tid&31)==0) red[tid>>5] = s;
    __syncthreads();
    if (tid == 0) {
        float t = 0.0f;
        for (int i = 0; i < 8; i++) t += red[i];
        atomicAdd(&g_scal[4], t);
    }
}

__global__ void scalarfin_k(const float* __restrict__ se, const float* __restrict__ ne,
                            float* __restrict__ out_snr)
{
    float ns = se[0]*RMC + g_scal[4]*0.01f;
    out_snr[0] = ns / (ne[0]*RMC);
}

extern "C" void kernel_launch(void* const* d_in, const int* in_sizes, int n_in,
                              void* d_out, int out_size)
{
    const float* I     = (const float*)d_in[0];
    const float* basis = (const float*)d_in[1];
    const float* hd    = (const float*)d_in[2];
    const float* l1h   = (const float*)d_in[3];
    const float* se    = (const float*)d_in[4];
    const float* ne    = (const float*)d_in[5];
    float* out = (float*)d_out;

    float *BT,*It,*a,*r,*S,*T0,*T1,*NB,*c,*aT;
    bf16 *Gh,*Gl,*Th0,*Tl0,*Th1,*Tl1,*BTh,*BTl,*bsh,*bsl,*Ith,*Itl,*rh,*rl,*aTh,*aTl;
    cudaGetSymbolAddress((void**)&BT, g_BT);
    cudaGetSymbolAddress((void**)&It, g_It);
    cudaGetSymbolAddress((void**)&a,  g_a);
    cudaGetSymbolAddress((void**)&r,  g_r);
    cudaGetSymbolAddress((void**)&S,  g_S);
    cudaGetSymbolAddress((void**)&T0, g_T0);
    cudaGetSymbolAddress((void**)&T1, g_T1);
    cudaGetSymbolAddress((void**)&NB, g_NB);
    cudaGetSymbolAddress((void**)&c,  g_c);
    cudaGetSymbolAddress((void**)&aT, g_aT);
    cudaGetSymbolAddress((void**)&Gh, g_Gh);
    cudaGetSymbolAddress((void**)&Gl, g_Gl);
    cudaGetSymbolAddress((void**)&Th0, g_Th0);
    cudaGetSymbolAddress((void**)&Tl0, g_Tl0);
    cudaGetSymbolAddress((void**)&Th1, g_Th1);
    cudaGetSymbolAddress((void**)&Tl1, g_Tl1);
    cudaGetSymbolAddress((void**)&BTh, g_BTh);
    cudaGetSymbolAddress((void**)&BTl, g_BTl);
    cudaGetSymbolAddress((void**)&bsh, g_bsh);
    cudaGetSymbolAddress((void**)&bsl, g_bsl);
    cudaGetSymbolAddress((void**)&Ith, g_Ith);
    cudaGetSymbolAddress((void**)&Itl, g_Itl);
    cudaGetSymbolAddress((void**)&rh, g_rh);
    cudaGetSymbolAddress((void**)&rl, g_rl);
    cudaGetSymbolAddress((void**)&aTh, g_aTh);
    cudaGetSymbolAddress((void**)&aTl, g_aTl);

    cudaFuncSetAttribute(persist4_k, cudaFuncAttributeMaxDynamicSharedMemorySize, DYN2);
    cudaFuncSetAttribute(mmant_k<0>, cudaFuncAttributeMaxDynamicSharedMemorySize, DYN);
    cudaFuncSetAttribute(mmant_k<1>, cudaFuncAttributeMaxDynamicSharedMemorySize, DYN);
    cudaFuncSetAttribute(mmant_k<2>, cudaFuncAttributeMaxDynamicSharedMemorySize, DYN);
    cudaFuncSetAttribute(mmant_k<3>, cudaFuncAttributeMaxDynamicSharedMemorySize, DYN);

    transpose_k<<<dim3(BD/32, ED/32), dim3(32,8)>>>(basis, BT, ED, BD);
    transpose_k<<<dim3(ED/32, BA/32), dim3(32,8)>>>(I, It, BA, ED);
    init_k<<<(BD*BA+255)/256, 256>>>();
    splitf_k<<<(int)(((size_t)BD*ED)/256), 256>>>(BT, BTh, BTl, BD*ED);
    splitf_k<<<(int)(((size_t)ED*BD)/256), 256>>>(basis, bsh, bsl, ED*BD);
    splitf_k<<<(ED*BA+255)/256, 256>>>(It, Ith, Itl, ED*BA);

    // G split = (BT * basis-as-Kmajor): [BD x BD], K=ED
    mmant_k<3><<<dim3(BD/64, BD/32), 256, DYN>>>(BTh, BTl, bsh, bsl,
        nullptr, nullptr, Gh, Gl, BD, ED);
    // c = B^T I_t : [BD x BA], K=ED (B-tile = It K-major)
    mmant_k<0><<<dim3(BA/64, BD/32), 256, DYN>>>(BTh, BTl, Ith, Itl,
        c, nullptr, nullptr, nullptr, BA, ED);
    // S = B B^T : [ED x ED], K=BD (B-tile = BT K-major)
    mmant_k<0><<<dim3(ED/64, ED/32), 256, DYN>>>(bsh, bsl, BTh, BTl,
        S, nullptr, nullptr, nullptr, ED, BD);
    copyN_k<<<(ED*ED+255)/256, 256>>>(S, T0, ED*ED);
    splitf_k<<<(ED*ED+255)/256, 256>>>(S, Th0, Tl0, ED*ED);
    float* fp[2] = {T0, T1};
    bf16* hp[2] = {Th0, Th1};
    bf16* lp[2] = {Tl0, Tl1};
    for (int i = 0; i < 6; i++) {
        diagmax_k<<<1, 1024>>>(fp[0]);
        mmant_k<1><<<dim3(ED/64, ED/32), 256, DYN>>>(hp[0], lp[0], hp[0], lp[0],
            fp[1], nullptr, hp[1], lp[1], ED, ED);
        float* tf = fp[0]; fp[0] = fp[1]; fp[1] = tf;
        bf16* th = hp[0]; hp[0] = hp[1]; hp[1] = th;
        bf16* tl = lp[0]; lp[0] = lp[1]; lp[1] = tl;
    }

    persist4_k<<<GRIDP, 128, DYN2>>>(basis);

    transpose_k<<<dim3(BA/32, BD/32), dim3(32,8)>>>(a, aT, BD, BA);
    splitf_k<<<(int)(((size_t)BA*BD)/256), 256>>>(aT, aTh, aTl, BA*BD);
    splitf_k<<<(ED*BA+255)/256, 256>>>(r, rh, rl, ED*BA);
    rowstats_k<<<BD, 128>>>(a, hd, l1h, out + O_HES, out + O_L1);
    // NB = basis + (H/BA) * (r a^T) / (hes+eps) : [ED x BD], K=BA
    mmant_k<2><<<dim3(BD/64, ED/32), 256, DYN>>>(rh, rl, aTh, aTl,
        NB, basis, nullptr, nullptr, BD, BA);
    colnorm1_k<<<dim3(BD/256, ED/128), 256>>>(NB);
    colnorm2_k<<<(ED*BD+255)/256, 256>>>(NB, out + O_BASIS);
    copy_a_k<<<(BD*BA+255)/256, 256>>>(a, out + O_A);
    sumI2_k<<<256, 256>>>(I);
    scalarfin_k<<<1, 1>>>(se, ne, out + O_SNR);
}

// round 13
// speedup vs baseline: 1.3777x; 1.3777x over previous
#include <cuda_runtime.h>
#include <cuda_bf16.h>
#include <cstdint>
#include <cstddef>

#define ED 1024
#define BD 2048
#define BA 128
#define NITER 500
#define LAMB_C 0.3f
#define H_C 0.005f
#define RMC 0.99f
#define LOWACT 0.001f
#define GRIDP 128

#define O_A     ((size_t)0)
#define O_BASIS ((size_t)(BD*BA))
#define O_HES   (O_BASIS + (size_t)ED*BD)
#define O_L1    (O_HES + BD)
#define O_SNR   (O_L1 + BD)

// shared smem layout (persist3_k and mmant_k): 4-stage ring, 144B rows
#define GH_O 0
#define GL_O 4608
#define AH_O 9216
#define AL_O 18432
#define BUFS 28672
#define DYN  (4*BUFS)

typedef __nv_bfloat16 bf16;

__device__ float g_BT[(size_t)BD*ED];
__device__ float g_It[(size_t)ED*BA];
__device__ float g_a [(size_t)BD*BA];
__device__ float g_a2[(size_t)BD*BA];
__device__ float g_c [(size_t)BD*BA];
__device__ float g_r [(size_t)ED*BA];
__device__ float g_S [(size_t)ED*ED];
__device__ float g_T0[(size_t)ED*ED];
__device__ float g_T1[(size_t)ED*ED];
__device__ float g_NB[(size_t)ED*BD];
__device__ float g_aT[(size_t)BA*BD];
__device__ bf16 g_Gh[(size_t)BD*BD];
__device__ bf16 g_Gl[(size_t)BD*BD];
__device__ bf16 g_ah0[(size_t)BD*BA];
__device__ bf16 g_ah1[(size_t)BD*BA];
__device__ bf16 g_al0[(size_t)BD*BA];
__device__ bf16 g_al1[(size_t)BD*BA];
__device__ bf16 g_Th0[(size_t)ED*ED];
__device__ bf16 g_Tl0[(size_t)ED*ED];
__device__ bf16 g_Th1[(size_t)ED*ED];
__device__ bf16 g_Tl1[(size_t)ED*ED];
__device__ bf16 g_BTh[(size_t)BD*ED];
__device__ bf16 g_BTl[(size_t)BD*ED];
__device__ bf16 g_bsh[(size_t)ED*BD];
__device__ bf16 g_bsl[(size_t)ED*BD];
__device__ bf16 g_Ith[(size_t)ED*BA];
__device__ bf16 g_Itl[(size_t)ED*BA];
__device__ bf16 g_rh[(size_t)ED*BA];
__device__ bf16 g_rl[(size_t)ED*BA];
__device__ bf16 g_aTh[(size_t)BA*BD];
__device__ bf16 g_aTl[(size_t)BA*BD];
__device__ float g_hes[BD];
__device__ float g_nsq[BD];
__device__ float g_v[ED];
__device__ float g_w[ED];
__device__ float g_scal[8];
__device__ unsigned g_cnt;
__device__ volatile unsigned g_gen;

__device__ __forceinline__ float sshrinkf(float v, float thr) {
    float t = fabsf(v) - thr;
    return t > 0.0f ? copysignf(t, v) : 0.0f;
}
__device__ __forceinline__ uint32_t smem_u32(const void* p) {
    uint32_t a;
    asm("{ .reg .u64 t; cvta.to.shared.u64 t, %1; cvt.u32.u64 %0, t; }" : "=r"(a) : "l"(p));
    return a;
}
#define LDSM4(r, ad) asm volatile( \
    "ldmatrix.sync.aligned.m8n8.x4.shared.b16 {%0,%1,%2,%3},[%4];" \
    : "=r"((r)[0]),"=r"((r)[1]),"=r"((r)[2]),"=r"((r)[3]) : "r"(ad))
#define LDSM4T(r, ad) asm volatile( \
    "ldmatrix.sync.aligned.m8n8.x4.trans.shared.b16 {%0,%1,%2,%3},[%4];" \
    : "=r"((r)[0]),"=r"((r)[1]),"=r"((r)[2]),"=r"((r)[3]) : "r"(ad))
#define MMA16816(c, a, b0, b1) asm volatile( \
    "mma.sync.aligned.m16n8k16.row.col.f32.bf16.bf16.f32 " \
    "{%0,%1,%2,%3},{%4,%5,%6,%7},{%8,%9},{%0,%1,%2,%3};" \
    : "+f"((c)[0]),"+f"((c)[1]),"+f"((c)[2]),"+f"((c)[3]) \
    : "r"((a)[0]),"r"((a)[1]),"r"((a)[2]),"r"((a)[3]),"r"(b0),"r"(b1))
#define CPA16(dst, src) asm volatile("cp.async.cg.shared.global [%0],[%1],16;" :: "r"(dst), "l"(src))
#define CPCOMMIT() asm volatile("cp.async.commit_group;" ::: "memory")
#define CPWAIT(n)  asm volatile("cp.async.wait_group %0;" :: "n"(n) : "memory")

__device__ __forceinline__ void gsync(unsigned gen) {
    __syncthreads();
    if (threadIdx.x == 0) {
        __threadfence();
        unsigned t = atomicAdd(&g_cnt, 1u);
        if (t == GRIDP - 1) { g_cnt = 0; __threadfence(); g_gen = gen; }
        else { while (g_gen < gen) { } __threadfence(); }
    }
    __syncthreads();
}

// =================== generic split-bf16 NT GEMM on mma ===================
// C[M,N] = (Ah+Al)[M,K] * (Bh+Bl) with B stored K-major [K][N].
// grid (N/64, M/32), 256 thr. EPI 0: Cf  1: Cf*s2+split  2: NB-update  3: split only
template<int EPI>
__global__ void __launch_bounds__(256, 1) mmant_k(
    const bf16* __restrict__ Ah, const bf16* __restrict__ Al,
    const bf16* __restrict__ Bh, const bf16* __restrict__ Bl,
    float* __restrict__ Cf, const float* __restrict__ Aux,
    bf16* __restrict__ Ch, bf16* __restrict__ Cl, int N, int K)
{
    extern __shared__ char dsm[];
    const int tid = threadIdx.x, w = tid >> 5, l = tid & 31;
    const int nt = blockIdx.x, mt = blockIdx.y;
    const int wm = w >> 2, wn = w & 3;
    const uint32_t smu = smem_u32(dsm);
    const uint32_t adA = (uint32_t)(wm*16 + (l & 15))*144 + ((l >> 4)*16);
    const uint32_t adB = (uint32_t)((l & 7) + ((l >> 3) & 1)*8)*144 + (wn*32 + (l >> 4)*16);
    const int KT = K >> 6;
    float acc0[4] = {0,0,0,0}, acc1[4] = {0,0,0,0};

    auto ISS = [&](int t) {
        uint32_t sb = smu + (uint32_t)(t & 3)*BUFS;
        int kc = t*64;
        { int r_ = tid >> 3, q = tid & 7;
          CPA16(sb + GH_O + r_*144 + q*16, Ah + (size_t)(mt*32 + r_)*K + kc + q*8);
          CPA16(sb + GL_O + r_*144 + q*16, Al + (size_t)(mt*32 + r_)*K + kc + q*8); }
        #pragma unroll
        for (int i = 0; i < 2; i++) {
            int u = tid*2 + i, r_ = u >> 3, q = u & 7;
            CPA16(sb + AH_O + r_*144 + q*16, Bh + (size_t)(kc + r_)*N + nt*64 + q*8);
            CPA16(sb + AL_O + r_*144 + q*16, Bl + (size_t)(kc + r_)*N + nt*64 + q*8);
        }
        CPCOMMIT();
    };
    ISS(0);
    if (KT > 1) ISS(1);
    if (KT > 2) ISS(2);

    #pragma unroll 1
    for (int t = 0; t < KT; t++) {
        int rem = ((t + 3 < KT) ? 3 : (KT - t)) - 1;
        if (rem >= 2) CPWAIT(2); else if (rem == 1) CPWAIT(1); else CPWAIT(0);
        __syncthreads();
        if (t + 3 < KT) ISS(t + 3);
        const uint32_t base = smu + (uint32_t)(t & 3)*BUFS;
        #pragma unroll
        for (int kq = 0; kq < 4; kq++) {
            uint32_t fah[4], fal[4], fbh[4], fbl[4];
            LDSM4(fah, base + GH_O + kq*32 + adA);
            LDSM4(fal, base + GL_O + kq*32 + adA);
            LDSM4T(fbh, base + AH_O + kq*16*144 + adB);
            LDSM4T(fbl, base + AL_O + kq*16*144 + adB);
            MMA16816(acc0, fah, fbh[0], fbh[1]);
            MMA16816(acc1, fah, fbh[2], fbh[3]);
            MMA16816(acc0, fah, fbl[0], fbl[1]);
            MMA16816(acc1, fah, fbl[2], fbl[3]);
            MMA16816(acc0, fal, fbh[0], fbh[1]);
            MMA16816(acc1, fal, fbh[2], fbh[3]);
        }
    }
    const float s2 = (EPI == 1) ? g_scal[3]*g_scal[3] : 1.0f;
    #pragma unroll
    for (int ntl = 0; ntl < 2; ntl++) {
        const float* ap = ntl ? acc1 : acc0;
        int gc = nt*64 + wn*16 + ntl*8 + (l & 3)*2;
        #pragma unroll
        for (int rr = 0; rr < 2; rr++) {
            int gr = mt*32 + wm*16 + (l >> 2) + rr*8;
            size_t idx = (size_t)gr*N + gc;
            float vx = ap[rr*2+0], vy = ap[rr*2+1];
            if (EPI == 0) {
                *(float2*)&Cf[idx] = make_float2(vx, vy);
            } else if (EPI == 1) {
                vx *= s2; vy *= s2;
                *(float2*)&Cf[idx] = make_float2(vx, vy);
                __nv_bfloat162 hp, lp;
                hp.x = __float2bfloat16(vx); hp.y = __float2bfloat16(vy);
                lp.x = __float2bfloat16(vx - __bfloat162float(hp.x));
                lp.y = __float2bfloat16(vy - __bfloat162float(hp.y));
                *(__nv_bfloat162*)&Ch[idx] = hp;
                *(__nv_bfloat162*)&Cl[idx] = lp;
            } else if (EPI == 2) {
                float2 ax = *(const float2*)&Aux[idx];
                Cf[idx]   = ax.x + (H_C/(float)BA)*vx/(g_hes[gc]   + LOWACT);
                Cf[idx+1] = ax.y + (H_C/(float)BA)*vy/(g_hes[gc+1] + LOWACT);
            } else {
                __nv_bfloat162 hp, lp;
                hp.x = __float2bfloat16(vx); hp.y = __float2bfloat16(vy);
                lp.x = __float2bfloat16(vx - __bfloat162float(hp.x));
                lp.y = __float2bfloat16(vy - __bfloat162float(hp.y));
                *(__nv_bfloat162*)&Ch[idx] = hp;
                *(__nv_bfloat162*)&Cl[idx] = lp;
            }
        }
    }
}

// ====== persistent (R11-proven): power iter + 500 Gram-ISTA + residual ======
__global__ void __launch_bounds__(256, 1) persist3_k(const float* __restrict__ basis)
{
    extern __shared__ char dsm[];
    __shared__ float red1[8], red2[8];
    __shared__ float sh_b;
    const int cta = blockIdx.x, tid = threadIdx.x;
    const int w = tid >> 5, l = tid & 31;
    unsigned gen = 0;
    const uint32_t smu = smem_u32(dsm);

    for (int pi = 0; pi < 9; pi++) {
        const float* M = (pi < 8) ? g_T0 : g_S;
        {
            int rw = cta*8 + w;
            const float* mr = M + (size_t)rw*ED;
            float s = 0.f;
            for (int j = l; j < ED; j += 32) s = fmaf(mr[j], g_v[j], s);
            #pragma unroll
            for (int o = 16; o; o >>= 1) s += __shfl_xor_sync(~0u, s, o);
            if (l == 0) g_w[rw] = s;
        }
        gen++; gsync(gen);
        if (cta == 0) {
            if (pi < 8) {
                float x[4], ss = 0.f;
                #pragma unroll
                for (int i = 0; i < 4; i++) { x[i] = g_w[tid*4+i]; ss = fmaf(x[i], x[i], ss); }
                #pragma unroll
                for (int o = 16; o; o >>= 1) ss += __shfl_xor_sync(~0u, ss, o);
                if (l == 0) red1[w] = ss;
                __syncthreads();
                if (tid == 0) {
                    float t = 0.f;
                    for (int i = 0; i < 8; i++) t += red1[i];
                    sh_b = rsqrtf(t);
                }
                __syncthreads();
                float rs = sh_b;
                #pragma unroll
                for (int i = 0; i < 4; i++) g_v[tid*4+i] = x[i]*rs;
            } else {
                float d1 = 0.f, d2 = 0.f;
                #pragma unroll
                for (int i = 0; i < 4; i++) {
                    float vv = g_v[tid*4+i], ww = g_w[tid*4+i];
                    d1 = fmaf(vv, ww, d1); d2 = fmaf(vv, vv, d2);
                }
                #pragma unroll
                for (int o = 16; o; o >>= 1) {
                    d1 += __shfl_xor_sync(~0u, d1, o);
                    d2 += __shfl_xor_sync(~0u, d2, o);
                }
                if (l == 0) { red1[w] = d1; red2[w] = d2; }
                __syncthreads();
                if (tid == 0) {
                    float a = 0.f, b = 0.f;
                    for (int i = 0; i < 8; i++) { a += red1[i]; b += red2[i]; }
                    float lam = a / b;
                    g_scal[0] = lam; g_scal[1] = 1.0f/lam; g_scal[2] = LAMB_C/lam;
                }
                __syncthreads();
            }
        }
        gen++; gsync(gen);
    }

    const float eta = g_scal[1], thr = g_scal[2];
    const int mt = cta >> 1, nh = cta & 1;
    const int wm = w >> 2, wn = w & 3;
    const uint32_t adA = (uint32_t)(wm*16 + (l & 15))*144 + ((l >> 4)*16);
    const uint32_t adB = (uint32_t)((l & 7) + ((l >> 3) & 1)*8)*144 + (wn*32 + (l >> 4)*16);
    const int gur = tid >> 3, guq = tid & 7;
    const uint32_t dG  = (uint32_t)gur*144 + guq*16;
    const uint32_t dA1 = (uint32_t)(gur+32)*144 + guq*16;
    const bf16* GhR = g_Gh + (size_t)(mt*32 + gur)*BD + guq*8;
    const bf16* GlR = g_Gl + (size_t)(mt*32 + gur)*BD + guq*8;

    for (int it = 0; it < NITER; it++) {
        const int cur = it & 1;
        const float* acur = cur ? g_a2 : g_a;
        float*       anxt = cur ? g_a  : g_a2;
        const bf16* ahc = cur ? g_ah1 : g_ah0;
        const bf16* alc = cur ? g_al1 : g_al0;
        bf16* ahn = cur ? g_ah0 : g_ah1;
        bf16* aln = cur ? g_al0 : g_al1;
        const bf16* aH = ahc + (size_t)gur*BA + nh*64 + guq*8;
        const bf16* aL = alc + (size_t)gur*BA + nh*64 + guq*8;

        float acc0[4] = {0,0,0,0}, acc1[4] = {0,0,0,0};
        auto ISS = [&](int t) {
            uint32_t sb = smu + (uint32_t)(t & 3)*BUFS;
            int kc = t*64;
            CPA16(sb + GH_O + dG,  GhR + kc);
            CPA16(sb + GL_O + dG,  GlR + kc);
            CPA16(sb + AH_O + dG,  aH + (size_t)kc*BA);
            CPA16(sb + AH_O + dA1, aH + (size_t)(kc+32)*BA);
            CPA16(sb + AL_O + dG,  aL + (size_t)kc*BA);
            CPA16(sb + AL_O + dA1, aL + (size_t)(kc+32)*BA);
            CPCOMMIT();
        };
        ISS(0); ISS(1); ISS(2);

        #pragma unroll 1
        for (int t = 0; t < 32; t++) {
            if (t < 30) CPWAIT(2); else if (t == 30) CPWAIT(1); else CPWAIT(0);
            __syncthreads();
            if (t + 3 < 32) ISS(t + 3);
            const uint32_t base = smu + (uint32_t)(t & 3)*BUFS;
            #pragma unroll
            for (int kq = 0; kq < 4; kq++) {
                uint32_t fah[4], fal[4], fbh[4], fbl[4];
                LDSM4(fah, base + GH_O + kq*32 + adA);
                LDSM4(fal, base + GL_O + kq*32 + adA);
                LDSM4T(fbh, base + AH_O + kq*16*144 + adB);
                LDSM4T(fbl, base + AL_O + kq*16*144 + adB);
                MMA16816(acc0, fah, fbh[0], fbh[1]);
                MMA16816(acc1, fah, fbh[2], fbh[3]);
                MMA16816(acc0, fah, fbl[0], fbl[1]);
                MMA16816(acc1, fah, fbl[2], fbl[3]);
                MMA16816(acc0, fal, fbh[0], fbh[1]);
                MMA16816(acc1, fal, fbh[2], fbh[3]);
            }
        }

        #pragma unroll
        for (int nt = 0; nt < 2; nt++) {
            const float* ap = nt ? acc1 : acc0;
            int gc = nh*64 + wn*16 + nt*8 + (l & 3)*2;
            #pragma unroll
            for (int rr = 0; rr < 2; rr++) {
                int gr = mt*32 + wm*16 + (l >> 2) + rr*8;
                size_t idx = (size_t)gr*BA + gc;
                float2 ao = *(const float2*)&acur[idx];
                float2 cv = *(const float2*)&g_c[idx];
                float vx = sshrinkf(ao.x + eta*(cv.x - ap[rr*2+0]), thr);
                float vy = sshrinkf(ao.y + eta*(cv.y - ap[rr*2+1]), thr);
                *(float2*)&anxt[idx] = make_float2(vx, vy);
                __nv_bfloat162 hp, lp;
                hp.x = __float2bfloat16(vx); hp.y = __float2bfloat16(vy);
                lp.x = __float2bfloat16(vx - __bfloat162float(hp.x));
                lp.y = __float2bfloat16(vy - __bfloat162float(hp.y));
                *(__nv_bfloat162*)&ahn[idx] = hp;
                *(__nv_bfloat162*)&aln[idx] = lp;
            }
        }
        gen++; gsync(gen);
    }

    // final residual: r = It - basis*a ; warp -> one row
    {
        const int rw = cta*8 + w;
        float4 racc = make_float4(0.f, 0.f, 0.f, 0.f);
        float* aS = (float*)dsm;
        float* bS = (float*)(dsm + 17024);
        for (int t = 0; t < 64; t++) {
            int k0 = t*32;
            float4 rv[4];
            #pragma unroll
            for (int i = 0; i < 4; i++) {
                int u = tid*4 + i, rr = u >> 5, q = u & 31;
                rv[i] = *(const float4*)&g_a[(size_t)(k0 + rr)*BA + q*4];
            }
            float bb = basis[(size_t)rw*BD + k0 + l];
            __syncthreads();
            #pragma unroll
            for (int i = 0; i < 4; i++) {
                int u = tid*4 + i, rr = u >> 5, q = u & 31;
                *(float4*)&aS[rr*132 + q*4] = rv[i];
            }
            bS[w*32 + l] = bb;
            __syncthreads();
            #pragma unroll 8
            for (int kk = 0; kk < 32; kk++) {
                float b_ = bS[w*32 + kk];
                float4 av = *(const float4*)&aS[kk*132 + l*4];
                racc.x = fmaf(b_, av.x, racc.x);
                racc.y = fmaf(b_, av.y, racc.y);
                racc.z = fmaf(b_, av.z, racc.z);
                racc.w = fmaf(b_, av.w, racc.w);
            }
        }
        float4 iv = *(const float4*)&g_It[(size_t)rw*BA + l*4];
        *(float4*)&g_r[(size_t)rw*BA + l*4] =
            make_float4(iv.x-racc.x, iv.y-racc.y, iv.z-racc.z, iv.w-racc.w);
    }
}

// ---------------- helpers ----------------
__global__ void transpose_k(const float* __restrict__ in, float* __restrict__ out,
                            int rows, int cols)
{
    __shared__ float sm[32][33];
    int bx = blockIdx.x*32, by = blockIdx.y*32;
    int tx = threadIdx.x, ty = threadIdx.y;
    #pragma unroll
    for (int j = 0; j < 32; j += 8)
        sm[ty+j][tx] = in[(size_t)(by+ty+j)*cols + bx+tx];
    __syncthreads();
    #pragma unroll
    for (int j = 0; j < 32; j += 8)
        out[(size_t)(bx+ty+j)*rows + by+tx] = sm[tx][ty+j];
}

__global__ void init_k() {
    int idx = blockIdx.x*256 + threadIdx.x;
    if (idx < BD*BA) {
        g_a[idx] = 0.0f;
        g_ah0[idx] = __float2bfloat16(0.0f);
        g_al0[idx] = __float2bfloat16(0.0f);
    }
    if (idx < ED) g_v[idx] = 1.0f;
    if (idx == 0) { g_scal[4] = 0.0f; g_cnt = 0; g_gen = 0; }
}

__global__ void splitf_k(const float* __restrict__ in, bf16* __restrict__ h,
                         bf16* __restrict__ lo, int n)
{
    int i = blockIdx.x*256 + threadIdx.x;
    if (i < n) {
        float g = in[i];
        bf16 hh = __float2bfloat16(g);
        h[i] = hh;
        lo[i] = __float2bfloat16(g - __bfloat162float(hh));
    }
}

__global__ void copyN_k(const float* __restrict__ in, float* __restrict__ out, int n) {
    int i = blockIdx.x*256 + threadIdx.x;
    if (i < n) out[i] = in[i];
}

__global__ void diagmax_k(const float* __restrict__ T) {
    __shared__ float red[32];
    int tid = threadIdx.x;
    float m = fabsf(T[(size_t)tid*ED + tid]);
    #pragma unroll
    for (int o = 16; o; o >>= 1) m = fmaxf(m, __shfl_xor_sync(~0u, m, o));
    if ((tid&31)==0) red[tid>>5] = m;
    __syncthreads();
    if (tid < 32) {
        float mm = red[tid];
        #pragma unroll
        for (int o = 16; o; o >>= 1) mm = fmaxf(mm, __shfl_xor_sync(~0u, mm, o));
        if (tid == 0) g_scal[3] = 1.0f / mm;
    }
}

__global__ void rowstats_k(const float* __restrict__ a, const float* __restrict__ hd,
                           const float* __restrict__ l1h,
                           float* __restrict__ out_hes, float* __restrict__ out_l1)
{
    __shared__ float s1s[4], s2s[4];
    int m = blockIdx.x, tid = threadIdx.x;
    float av = a[(size_t)m*BA + tid];
    float s1 = fabsf(av), s2 = av*av;
    #pragma unroll
    for (int o = 16; o; o >>= 1) {
        s1 += __shfl_xor_sync(~0u, s1, o);
        s2 += __shfl_xor_sync(~0u, s2, o);
    }
    if ((tid&31)==0) { s1s[tid>>5]=s1; s2s[tid>>5]=s2; }
    __syncthreads();
    if (tid == 0) {
        float t1 = s1s[0]+s1s[1]+s1s[2]+s1s[3];
        float t2 = s2s[0]+s2s[1]+s2s[2]+s2s[3];
        float he = hd[m]*RMC + t2*(1.0f/(BA*100.0f));
        out_l1[m] = l1h[m]*RMC + t1*(1.0f/(BA*100.0f));
        out_hes[m] = he;
        g_hes[m] = he;
        g_nsq[m] = 0.0f;
    }
}

__global__ void colnorm1_k(const float* __restrict__ NB) {
    int col = blockIdx.x*256 + threadIdx.x;
    int r0 = blockIdx.y*128;
    float s = 0.0f;
    for (int r = r0; r < r0+128; r++) {
        float v = NB[(size_t)r*BD + col];
        s = fmaf(v, v, s);
    }
    atomicAdd(&g_nsq[col], s);
}

__global__ void colnorm2_k(const float* __restrict__ NB, float* __restrict__ out) {
    int i = blockIdx.x*blockDim.x + threadIdx.x;
    if (i < ED*BD) out[i] = NB[i] * rsqrtf(g_nsq[i & (BD-1)]);
}

__global__ void copy_a_k(const float* __restrict__ a, float* __restrict__ out) {
    int i = blockIdx.x*blockDim.x + threadIdx.x;
    if (i < BD*BA) out[i] = a[i];
}

__global__ void sumI2_k(const float* __restrict__ I) {
    __shared__ float red[8];
    int tid = threadIdx.x;
    float s = 0.0f;
    for (int i = blockIdx.x*blockDim.x + tid; i < ED*BA; i += gridDim.x*blockDim.x) {
        float v = I[i];
        s = fmaf(v, v, s);
    }
    #pragma unroll
    for (int o = 16; o; o >>= 1) s += __shfl_xor_sync(~0u, s, o);
    if ((tid&31)==0) red[tid>>5] = s;
    __syncthreads();
    if (tid == 0) {
        float t = 0.0f;
        for (int i = 0; i < 8; i++) t += red[i];
        atomicAdd(&g_scal[4], t);
    }
}

__global__ void scalarfin_k(const float* __restrict__ se, const float* __restrict__ ne,
                            float* __restrict__ out_snr)
{
    float ns = se[0]*RMC + g_scal[4]*0.01f;
    out_snr[0] = ns / (ne[0]*RMC);
}

extern "C" void kernel_launch(void* const* d_in, const int* in_sizes, int n_in,
                              void* d_out, int out_size)
{
    const float* I     = (const float*)d_in[0];
    const float* basis = (const float*)d_in[1];
    const float* hd    = (const float*)d_in[2];
    const float* l1h   = (const float*)d_in[3];
    const float* se    = (const float*)d_in[4];
    const float* ne    = (const float*)d_in[5];
    float* out = (float*)d_out;

    float *BT,*It,*a,*r,*S,*T0,*T1,*NB,*c,*aT;
    bf16 *Gh,*Gl,*Th0,*Tl0,*Th1,*Tl1,*BTh,*BTl,*bsh,*bsl,*Ith,*Itl,*rh,*rl,*aTh,*aTl;
    cudaGetSymbolAddress((void**)&BT, g_BT);
    cudaGetSymbolAddress((void**)&It, g_It);
    cudaGetSymbolAddress((void**)&a,  g_a);
    cudaGetSymbolAddress((void**)&r,  g_r);
    cudaGetSymbolAddress((void**)&S,  g_S);
    cudaGetSymbolAddress((void**)&T0, g_T0);
    cudaGetSymbolAddress((void**)&T1, g_T1);
    cudaGetSymbolAddress((void**)&NB, g_NB);
    cudaGetSymbolAddress((void**)&c,  g_c);
    cudaGetSymbolAddress((void**)&aT, g_aT);
    cudaGetSymbolAddress((void**)&Gh, g_Gh);
    cudaGetSymbolAddress((void**)&Gl, g_Gl);
    cudaGetSymbolAddress((void**)&Th0, g_Th0);
    cudaGetSymbolAddress((void**)&Tl0, g_Tl0);
    cudaGetSymbolAddress((void**)&Th1, g_Th1);
    cudaGetSymbolAddress((void**)&Tl1, g_Tl1);
    cudaGetSymbolAddress((void**)&BTh, g_BTh);
    cudaGetSymbolAddress((void**)&BTl, g_BTl);
    cudaGetSymbolAddress((void**)&bsh, g_bsh);
    cudaGetSymbolAddress((void**)&bsl, g_bsl);
    cudaGetSymbolAddress((void**)&Ith, g_Ith);
    cudaGetSymbolAddress((void**)&Itl, g_Itl);
    cudaGetSymbolAddress((void**)&rh, g_rh);
    cudaGetSymbolAddress((void**)&rl, g_rl);
    cudaGetSymbolAddress((void**)&aTh, g_aTh);
    cudaGetSymbolAddress((void**)&aTl, g_aTl);

    cudaFuncSetAttribute(persist3_k, cudaFuncAttributeMaxDynamicSharedMemorySize, DYN);
    cudaFuncSetAttribute(mmant_k<0>, cudaFuncAttributeMaxDynamicSharedMemorySize, DYN);
    cudaFuncSetAttribute(mmant_k<1>, cudaFuncAttributeMaxDynamicSharedMemorySize, DYN);
    cudaFuncSetAttribute(mmant_k<2>, cudaFuncAttributeMaxDynamicSharedMemorySize, DYN);
    cudaFuncSetAttribute(mmant_k<3>, cudaFuncAttributeMaxDynamicSharedMemorySize, DYN);

    transpose_k<<<dim3(BD/32, ED/32), dim3(32,8)>>>(basis, BT, ED, BD);
    transpose_k<<<dim3(ED/32, BA/32), dim3(32,8)>>>(I, It, BA, ED);
    init_k<<<(BD*BA+255)/256, 256>>>();
    splitf_k<<<(int)(((size_t)BD*ED)/256), 256>>>(BT, BTh, BTl, BD*ED);
    splitf_k<<<(int)(((size_t)ED*BD)/256), 256>>>(basis, bsh, bsl, ED*BD);
    splitf_k<<<(ED*BA+255)/256, 256>>>(It, Ith, Itl, ED*BA);

    // G split = B^T B : [BD x BD], K=ED (B-tile = basis K-major)
    mmant_k<3><<<dim3(BD/64, BD/32), 256, DYN>>>(BTh, BTl, bsh, bsl,
        nullptr, nullptr, Gh, Gl, BD, ED);
    // c = B^T I_t : [BD x BA], K=ED
    mmant_k<0><<<dim3(BA/64, BD/32), 256, DYN>>>(BTh, BTl, Ith, Itl,
        c, nullptr, nullptr, nullptr, BA, ED);
    // S = B B^T : [ED x ED], K=BD
    mmant_k<0><<<dim3(ED/64, ED/32), 256, DYN>>>(bsh, bsl, BTh, BTl,
        S, nullptr, nullptr, nullptr, ED, BD);
    copyN_k<<<(ED*ED+255)/256, 256>>>(S, T0, ED*ED);
    splitf_k<<<(ED*ED+255)/256, 256>>>(S, Th0, Tl0, ED*ED);
    float* fp[2] = {T0, T1};
    bf16* hp[2] = {Th0, Th1};
    bf16* lp[2] = {Tl0, Tl1};
    for (int i = 0; i < 6; i++) {
        diagmax_k<<<1, 1024>>>(fp[0]);
        mmant_k<1><<<dim3(ED/64, ED/32), 256, DYN>>>(hp[0], lp[0], hp[0], lp[0],
            fp[1], nullptr, hp[1], lp[1], ED, ED);
        float* tf = fp[0]; fp[0] = fp[1]; fp[1] = tf;
        bf16* th = hp[0]; hp[0] = hp[1]; hp[1] = th;
        bf16* tl = lp[0]; lp[0] = lp[1]; lp[1] = tl;
    }

    persist3_k<<<GRIDP, 256, DYN>>>(basis);

    transpose_k<<<dim3(BA/32, BD/32), dim3(32,8)>>>(a, aT, BD, BA);
    splitf_k<<<(int)(((size_t)BA*BD)/256), 256>>>(aT, aTh, aTl, BA*BD);
    splitf_k<<<(ED*BA+255)/256, 256>>>(r, rh, rl, ED*BA);
    rowstats_k<<<BD, 128>>>(a, hd, l1h, out + O_HES, out + O_L1);
    // NB = basis + (H/BA) * (r a^T) / (hes+eps) : [ED x BD], K=BA
    mmant_k<2><<<dim3(BD/64, ED/32), 256, DYN>>>(rh, rl, aTh, aTl,
        NB, basis, nullptr, nullptr, BD, BA);
    colnorm1_k<<<dim3(BD/256, ED/128), 256>>>(NB);
    colnorm2_k<<<(ED*BD+255)/256, 256>>>(NB, out + O_BASIS);
    copy_a_k<<<(BD*BA+255)/256, 256>>>(a, out + O_A);
    sumI2_k<<<256, 256>>>(I);
    scalarfin_k<<<1, 1>>>(se, ne, out + O_SNR);
}